// round 8
// baseline (speedup 1.0000x reference)
#include <cuda_runtime.h>

// BoidPolicy: all-pairs boids on a unit torus, N=8192, out acc [N,2] f32.
//
// Pipeline (graph-capturable, allocation-free, 4 launches):
//  kA: 16x16 cell ids (snake rows) + per-block smem-atomic ranks + histograms
//  kB: prefix sums -> scatter offsets (single block)
//  kC: scatter into sorted packed SoA (float4 = xA,xB,yA,yB per j-pair) + cell byte + orig idx
//  k1: per 32-i tile (1024 threads / 32 warps): cull 256 cell rects vs tile bbox
//      -> pair live mask -> block-compacted u16 pair list -> 32 warps take
//      contiguous segments, unroll-4 batched loads -> f32x2 math -> reduce -> epilogue

#define NB      8192
#define NCELL   256
#define NBLKA   32
#define NTILE   256
#define TPB1    1024
#define NWARP   32

#define SEP2F   4e-4f
#define PERC2F  0.04f
#define EPSF    1e-8f
#define MAGIC   12582912.0f   // 1.5 * 2^23
#define FULLM   0xffffffffu

typedef unsigned long long u64;
typedef unsigned short u16;

__device__ float4 g_pos4[NB / 2];       // sorted packed (xA,xB,yA,yB)
__device__ float4 g_vel4[NB / 2];
__device__ int    g_orig[NB];
__device__ uint4  g_scellv[NB / 16];    // sorted cell ids, 1 byte per boid
__device__ int    g_cellid[NB];
__device__ int    g_lrank[NB];
__device__ int    g_cnt[NBLKA * NCELL];
__device__ int    g_off[NBLKA * NCELL];

__device__ __forceinline__ u64 pack2(float lo, float hi) {
    u64 r; asm("mov.b64 %0,{%1,%2};" : "=l"(r) : "f"(lo), "f"(hi)); return r;
}
__device__ __forceinline__ void unpack2(u64 v, float& lo, float& hi) {
    asm("mov.b64 {%0,%1},%2;" : "=f"(lo), "=f"(hi) : "l"(v));
}
__device__ __forceinline__ u64 f2add(u64 a, u64 b) {
    u64 d; asm("add.rn.f32x2 %0,%1,%2;" : "=l"(d) : "l"(a), "l"(b)); return d;
}
__device__ __forceinline__ u64 f2mul(u64 a, u64 b) {
    u64 d; asm("mul.rn.f32x2 %0,%1,%2;" : "=l"(d) : "l"(a), "l"(b)); return d;
}
__device__ __forceinline__ u64 f2fma(u64 a, u64 b, u64 c) {
    u64 d; asm("fma.rn.f32x2 %0,%1,%2,%3;" : "=l"(d) : "l"(a), "l"(b), "l"(c)); return d;
}
// per-half: (t >= 0) ? 1.0f : 0.0f  (exact: copysign(0.5,t)+0.5)
__device__ __forceinline__ u64 f2mask(u64 t, u64 half2) {
    u64 s = (t & 0x8000000080000000ULL) | 0x3F0000003F000000ULL;
    return f2add(s, half2);
}
__device__ __forceinline__ float wrap1(float d) { return d - rintf(d); }
__device__ __forceinline__ float getX(const float* P, int idx) {
    return P[(idx >> 1) * 4 + (idx & 1)];
}
__device__ __forceinline__ float getY(const float* P, int idx) {
    return P[(idx >> 1) * 4 + 2 + (idx & 1)];
}

// ---------------- kA: cell ids + ranks + per-block histograms ----------------
__global__ void kA_cells(const float2* __restrict__ pos)
{
    __shared__ int hist[NCELL];
    const int tid = threadIdx.x;
    hist[tid] = 0;
    __syncthreads();

    const int e = blockIdx.x * 256 + tid;
    const float2 p = pos[e];
    int cx = (int)(p.x * 16.0f); cx = cx < 0 ? 0 : (cx > 15 ? 15 : cx);
    int cy = (int)(p.y * 16.0f); cy = cy < 0 ? 0 : (cy > 15 ? 15 : cy);
    const int lx   = (cy & 1) ? (15 - cx) : cx;       // snake order
    const int cell = (cy << 4) | lx;

    const int r = atomicAdd(&hist[cell], 1);
    g_cellid[e] = cell;
    g_lrank[e]  = r;
    __syncthreads();

    g_cnt[blockIdx.x * NCELL + tid] = hist[tid];
}

// ---------------- kB: prefix sums -> scatter offsets (1 block, 256 thr) ----------------
__global__ void kB_prefix()
{
    const int c = threadIdx.x;
    int run = 0;
    for (int g = 0; g < NBLKA; ++g) {
        const int v = g_cnt[g * NCELL + c];
        g_off[g * NCELL + c] = run;
        run += v;
    }
    __shared__ int wsum[8];
    __shared__ int wbase[8];
    const int lane = c & 31, w = c >> 5;
    int s = run;
    #pragma unroll
    for (int o = 1; o < 32; o <<= 1) {
        const int t = __shfl_up_sync(FULLM, s, o);
        if (lane >= o) s += t;
    }
    if (lane == 31) wsum[w] = s;
    __syncthreads();
    if (c == 0) {
        int acc = 0;
        #pragma unroll
        for (int k = 0; k < 8; ++k) { wbase[k] = acc; acc += wsum[k]; }
    }
    __syncthreads();
    const int base = wbase[w] + s - run;
    for (int g = 0; g < NBLKA; ++g) g_off[g * NCELL + c] += base;
}

// ---------------- kC: scatter into sorted packed SoA ----------------
__global__ void kC_scatter(const float2* __restrict__ pos,
                           const float2* __restrict__ vel)
{
    const int e    = blockIdx.x * 256 + threadIdx.x;
    const int cell = g_cellid[e];
    const int dst  = g_off[(e >> 8) * NCELL + cell] + g_lrank[e];
    const float2 p = pos[e];
    const float2 v = vel[e];
    float* P = (float*)g_pos4;
    float* V = (float*)g_vel4;
    const int b = (dst >> 1) * 4 + (dst & 1);
    P[b] = p.x;  P[b + 2] = p.y;
    V[b] = v.x;  V[b + 2] = v.y;
    g_orig[dst] = e;
    ((unsigned char*)g_scellv)[dst] = (unsigned char)cell;
}

// ---------------- k1: cull + compact + unrolled pair math + epilogue ----------------
#define PAIR_BODY(PJ, VJ)                                                     \
    {                                                                         \
        const u64 dx2 = f2add((PJ).x, nxi2);                                  \
        const u64 rxp = f2add(f2add(dx2, C2), nC2);                           \
        const u64 dwx = f2fma(rxp, nOne2, dx2);                               \
        const u64 dy2 = f2add((PJ).y, nyi2);                                  \
        const u64 ryp = f2add(f2add(dy2, C2), nC2);                           \
        const u64 dwy = f2fma(ryp, nOne2, dy2);                               \
        const u64 d2  = f2fma(dwy, dwy, f2mul(dwx, dwx));                     \
        const u64 mp  = f2mask(f2fma(d2, nOne2, perc2c), half2);              \
        const u64 ms  = f2mask(f2fma(d2, nOne2, sep2c),  half2);              \
        Px2 = f2fma(dwx, mp, Px2);                                            \
        Py2 = f2fma(dwy, mp, Py2);                                            \
        Vx2 = f2fma((VJ).x, mp, Vx2);                                         \
        Vy2 = f2fma((VJ).y, mp, Vy2);                                         \
        Cn2 = f2add(Cn2, mp);                                                 \
        Sx2 = f2fma(dwx, ms, Sx2);                                            \
        Sy2 = f2fma(dwy, ms, Sy2);                                            \
    }

__global__ __launch_bounds__(TPB1)
void k1_main(const float2* __restrict__ vel,
             const float2* __restrict__ noise,
             const float*  __restrict__ w_sep,
             const float*  __restrict__ w_ali,
             const float*  __restrict__ w_coh,
             const float*  __restrict__ w_ns,
             float2*       __restrict__ out)
{
    __shared__ unsigned s_mask[8];         // 256-bit live-cell mask
    __shared__ int      s_scan[NWARP];
    __shared__ int      s_total;
    __shared__ u16      s_pairs[NB / 2];
    __shared__ float    red[NWARP][32][8];

    const int tid  = threadIdx.x;
    const int lane = tid & 31;
    const int w    = tid >> 5;
    const int g    = blockIdx.x;           // i-tile
    const int i    = g * 32 + lane;        // every warp holds the same 32 i's

    const float* P = (const float*)g_pos4;
    const float pix = getX(P, i);
    const float piy = getY(P, i);

    // --- tile bbox (each warp computes an identical copy via shuffles) ---
    const float x0 = __shfl_sync(FULLM, pix, 0);
    const float y0 = __shfl_sync(FULLM, piy, 0);
    const float rx = wrap1(pix - x0);
    const float ry = wrap1(piy - y0);
    float mnx = rx, mxx = rx, mny = ry, mxy = ry;
    #pragma unroll
    for (int o = 16; o; o >>= 1) {
        mnx = fminf(mnx, __shfl_xor_sync(FULLM, mnx, o));
        mxx = fmaxf(mxx, __shfl_xor_sync(FULLM, mxx, o));
        mny = fminf(mny, __shfl_xor_sync(FULLM, mny, o));
        mxy = fmaxf(mxy, __shfl_xor_sync(FULLM, mxy, o));
    }
    const float bcx = x0 + 0.5f * (mnx + mxx);
    const float bcy = y0 + 0.5f * (mny + mxy);
    const float bhx = 0.5f * (mxx - mnx);
    const float bhy = 0.5f * (mxy - mny);

    // --- cull: threads 0..255 test static rect of cell tid ---
    if (tid < 256) {
        const int cy = tid >> 4;
        const int lx = tid & 15;
        const int cx = (cy & 1) ? (15 - lx) : lx;
        const float ccx = (cx + 0.5f) * (1.0f / 16.0f);
        const float ccy = (cy + 0.5f) * (1.0f / 16.0f);
        const float gx = fmaxf(0.0f, fabsf(wrap1(bcx - ccx)) - bhx - (1.0f / 32.0f) - 1e-5f);
        const float gy = fmaxf(0.0f, fabsf(wrap1(bcy - ccy)) - bhy - (1.0f / 32.0f) - 1e-5f);
        const bool live = (gx * gx + gy * gy) <= PERC2F;
        const unsigned m = __ballot_sync(FULLM, live);
        if (lane == 0) s_mask[w] = m;
    }
    __syncthreads();

    // --- pair-level liveness: thread t owns pairs [4t, 4t+4) = boids [8t, 8t+8) ---
    unsigned pl = 0;
    {
        const uint2 cv = ((const uint2*)g_scellv)[tid];
        const unsigned cw[2] = {cv.x, cv.y};
        #pragma unroll
        for (int q = 0; q < 2; ++q) {
            const unsigned word = cw[q];
            #pragma unroll
            for (int h = 0; h < 2; ++h) {
                const unsigned ca = (word >> (h * 16)) & 0xffu;
                const unsigned cb = (word >> (h * 16 + 8)) & 0xffu;
                const unsigned lv = ((s_mask[ca >> 5] >> (ca & 31)) |
                                     (s_mask[cb >> 5] >> (cb & 31))) & 1u;
                pl |= lv << (q * 2 + h);
            }
        }
    }
    const int cntp = __popc(pl);
    int s = cntp;
    #pragma unroll
    for (int o = 1; o < 32; o <<= 1) {
        const int t = __shfl_up_sync(FULLM, s, o);
        if (lane >= o) s += t;
    }
    if (lane == 31) s_scan[w] = s;
    __syncthreads();
    if (tid == 0) {
        int acc = 0;
        #pragma unroll
        for (int k = 0; k < NWARP; ++k) { const int v = s_scan[k]; s_scan[k] = acc; acc += v; }
        s_total = acc;
    }
    __syncthreads();
    {
        int ofs = s_scan[w] + s - cntp;
        unsigned m2 = pl;
        while (m2) {
            const int b = __ffs(m2) - 1;
            m2 &= m2 - 1;
            s_pairs[ofs++] = (u16)(tid * 4 + b);
        }
    }
    __syncthreads();
    const int total = s_total;

    // --- main pair loop: warp w takes a contiguous segment, unroll 4 ---
    const u64 nxi2   = pack2(-pix, -pix);
    const u64 nyi2   = pack2(-piy, -piy);
    const u64 C2     = pack2( MAGIC,  MAGIC);
    const u64 nC2    = pack2(-MAGIC, -MAGIC);
    const u64 nOne2  = pack2(-1.0f, -1.0f);
    const u64 half2  = pack2(0.5f, 0.5f);
    const u64 sep2c  = pack2(SEP2F, SEP2F);
    const u64 perc2c = pack2(PERC2F, PERC2F);

    u64 Sx2 = 0, Sy2 = 0, Px2 = 0, Py2 = 0, Vx2 = 0, Vy2 = 0, Cn2 = 0;

    const ulonglong2* __restrict__ PP = (const ulonglong2*)g_pos4;
    const ulonglong2* __restrict__ VV = (const ulonglong2*)g_vel4;

    int k          = (total * w) >> 5;     // NWARP = 32
    const int kend = (total * (w + 1)) >> 5;

    for (; k + 3 < kend; k += 4) {
        const int i0 = s_pairs[k + 0];
        const int i1 = s_pairs[k + 1];
        const int i2 = s_pairs[k + 2];
        const int i3 = s_pairs[k + 3];
        const ulonglong2 pj0 = PP[i0];
        const ulonglong2 pj1 = PP[i1];
        const ulonglong2 pj2 = PP[i2];
        const ulonglong2 pj3 = PP[i3];
        const ulonglong2 vj0 = VV[i0];
        const ulonglong2 vj1 = VV[i1];
        const ulonglong2 vj2 = VV[i2];
        const ulonglong2 vj3 = VV[i3];
        PAIR_BODY(pj0, vj0)
        PAIR_BODY(pj1, vj1)
        PAIR_BODY(pj2, vj2)
        PAIR_BODY(pj3, vj3)
    }
    for (; k < kend; ++k) {
        const int i0 = s_pairs[k];
        const ulonglong2 pj0 = PP[i0];
        const ulonglong2 vj0 = VV[i0];
        PAIR_BODY(pj0, vj0)
    }

    // --- smem reduce (deterministic) + epilogue ---
    float a, b;
    unpack2(Sx2, a, b);  red[w][lane][0] = a + b;
    unpack2(Sy2, a, b);  red[w][lane][1] = a + b;
    unpack2(Px2, a, b);  red[w][lane][2] = a + b;
    unpack2(Py2, a, b);  red[w][lane][3] = a + b;
    unpack2(Vx2, a, b);  red[w][lane][4] = a + b;
    unpack2(Vy2, a, b);  red[w][lane][5] = a + b;
    unpack2(Cn2, a, b);  red[w][lane][6] = a + b;
    __syncthreads();

    if (tid < 32) {
        float s7[7];
        #pragma unroll
        for (int comp = 0; comp < 7; ++comp) {
            float acc = 0.0f;
            #pragma unroll
            for (int sg = 0; sg < NWARP; ++sg) acc += red[sg][tid][comp];
            s7[comp] = acc;
        }

        const float Sx = s7[0], Sy = s7[1], Px = s7[2], Py = s7[3];
        const float Vx = s7[4], Vy = s7[5];
        const float C  = s7[6] - 1.0f;       // remove self

        const int orig = g_orig[g * 32 + tid];
        const float2 vi = vel[orig];
        const float2 nz = noise[orig];

        float nrm = sqrtf(Sx * Sx + Sy * Sy);
        float inv = 1.0f / fmaxf(nrm, EPSF);
        const float sepx = -Sx * inv;
        const float sepy = -Sy * inv;

        const float invC = 1.0f / C;

        const float avx = (Vx - vi.x) * invC - vi.x;
        const float avy = (Vy - vi.y) * invC - vi.y;
        nrm = sqrtf(avx * avx + avy * avy);
        inv = 1.0f / fmaxf(nrm, EPSF);
        const float alix = avx * inv;
        const float aliy = avy * inv;

        const float cx2 = Px * invC;
        const float cy2 = Py * invC;
        nrm = sqrtf(cx2 * cx2 + cy2 * cy2);
        inv = 1.0f / fmaxf(nrm, EPSF);
        const float cohx = cx2 * inv;
        const float cohy = cy2 * inv;

        const float ws = *w_sep;
        const float wa = *w_ali;
        const float wc = *w_coh;
        const float wn = *w_ns;

        float ax = ws * sepx + wa * alix + wc * cohx + wn * nz.x;
        float ay = ws * sepy + wa * aliy + wc * cohy + wn * nz.y;

        nrm = sqrtf(ax * ax + ay * ay);
        if (nrm > 1.0f) {
            const float sc = 1.0f / fmaxf(nrm, EPSF);
            ax *= sc;
            ay *= sc;
        }

        out[orig] = make_float2(ax, ay);
    }
}

extern "C" void kernel_launch(void* const* d_in, const int* in_sizes, int n_in,
                              void* d_out, int out_size)
{
    const float2* pos   = (const float2*)d_in[0];
    const float2* vel   = (const float2*)d_in[1];
    const float2* noise = (const float2*)d_in[2];
    const float*  wsep  = (const float*)d_in[3];
    const float*  wali  = (const float*)d_in[4];
    const float*  wcoh  = (const float*)d_in[5];
    const float*  wns   = (const float*)d_in[6];
    float2* out = (float2*)d_out;

    kA_cells  <<<NBLKA, 256>>>(pos);
    kB_prefix <<<1, 256>>>();
    kC_scatter<<<NBLKA, 256>>>(pos, vel);
    k1_main   <<<NTILE, TPB1>>>(vel, noise, wsep, wali, wcoh, wns, out);
}

// round 9
// speedup vs baseline: 1.0327x; 1.0327x over previous
#include <cuda_runtime.h>

// BoidPolicy: all-pairs boids on a unit torus, N=8192, out acc [N,2] f32.
//
// Pipeline (graph-capturable, allocation-free, 4 launches):
//  kA: 16x16 cell ids (snake rows) + ranks + histograms; zeroes per-tile tickets
//  kB: prefix sums -> scatter offsets (single block)
//  kC: scatter into sorted packed SoA (float4 = xA,xB,yA,yB per j-pair) + cell byte + orig idx
//  k1: TWO blocks per 32-i tile (512 thr each): both cull+compact the tile's pair
//      list, split it by parity; partials -> global; last-arriving block (ticket)
//      combines part0+part1 and runs the fused epilogue.

#define NB      8192
#define NCELL   256
#define NBLKA   32
#define NTILE   256
#define TPB1    512
#define NWARP   16            // warps per block
#define NSEG    32            // total segments per tile (2 blocks x 16 warps)

#define SEP2F   4e-4f
#define PERC2F  0.04f
#define EPSF    1e-8f
#define MAGIC   12582912.0f   // 1.5 * 2^23
#define FULLM   0xffffffffu

typedef unsigned long long u64;
typedef unsigned short u16;

__device__ float4 g_pos4[NB / 2];       // sorted packed (xA,xB,yA,yB)
__device__ float4 g_vel4[NB / 2];
__device__ int    g_orig[NB];
__device__ uint4  g_scellv[NB / 16];    // sorted cell ids, 1 byte per boid
__device__ int    g_cellid[NB];
__device__ int    g_lrank[NB];
__device__ int    g_cnt[NBLKA * NCELL];
__device__ int    g_off[NBLKA * NCELL];
__device__ float  g_part[2][7][NB];     // [parity][comp][sorted boid]
__device__ int    g_ticket[NTILE];

__device__ __forceinline__ u64 pack2(float lo, float hi) {
    u64 r; asm("mov.b64 %0,{%1,%2};" : "=l"(r) : "f"(lo), "f"(hi)); return r;
}
__device__ __forceinline__ void unpack2(u64 v, float& lo, float& hi) {
    asm("mov.b64 {%0,%1},%2;" : "=f"(lo), "=f"(hi) : "l"(v));
}
__device__ __forceinline__ u64 f2add(u64 a, u64 b) {
    u64 d; asm("add.rn.f32x2 %0,%1,%2;" : "=l"(d) : "l"(a), "l"(b)); return d;
}
__device__ __forceinline__ u64 f2mul(u64 a, u64 b) {
    u64 d; asm("mul.rn.f32x2 %0,%1,%2;" : "=l"(d) : "l"(a), "l"(b)); return d;
}
__device__ __forceinline__ u64 f2fma(u64 a, u64 b, u64 c) {
    u64 d; asm("fma.rn.f32x2 %0,%1,%2,%3;" : "=l"(d) : "l"(a), "l"(b), "l"(c)); return d;
}
// per-half: (t >= 0) ? 1.0f : 0.0f  (exact: copysign(0.5,t)+0.5)
__device__ __forceinline__ u64 f2mask(u64 t, u64 half2) {
    u64 s = (t & 0x8000000080000000ULL) | 0x3F0000003F000000ULL;
    return f2add(s, half2);
}
__device__ __forceinline__ float wrap1(float d) { return d - rintf(d); }
__device__ __forceinline__ float getX(const float* P, int idx) {
    return P[(idx >> 1) * 4 + (idx & 1)];
}
__device__ __forceinline__ float getY(const float* P, int idx) {
    return P[(idx >> 1) * 4 + 2 + (idx & 1)];
}

// ---------------- kA: cell ids + ranks + histograms (+ ticket zero) ----------------
__global__ void kA_cells(const float2* __restrict__ pos)
{
    __shared__ int hist[NCELL];
    const int tid = threadIdx.x;
    hist[tid] = 0;
    if (blockIdx.x == 0) g_ticket[tid] = 0;
    __syncthreads();

    const int e = blockIdx.x * 256 + tid;
    const float2 p = pos[e];
    int cx = (int)(p.x * 16.0f); cx = cx < 0 ? 0 : (cx > 15 ? 15 : cx);
    int cy = (int)(p.y * 16.0f); cy = cy < 0 ? 0 : (cy > 15 ? 15 : cy);
    const int lx   = (cy & 1) ? (15 - cx) : cx;       // snake order
    const int cell = (cy << 4) | lx;

    const int r = atomicAdd(&hist[cell], 1);
    g_cellid[e] = cell;
    g_lrank[e]  = r;
    __syncthreads();

    g_cnt[blockIdx.x * NCELL + tid] = hist[tid];
}

// ---------------- kB: prefix sums -> scatter offsets (1 block, 256 thr) ----------------
__global__ void kB_prefix()
{
    const int c = threadIdx.x;
    int run = 0;
    for (int g = 0; g < NBLKA; ++g) {
        const int v = g_cnt[g * NCELL + c];
        g_off[g * NCELL + c] = run;
        run += v;
    }
    __shared__ int wsum[8];
    __shared__ int wbase[8];
    const int lane = c & 31, w = c >> 5;
    int s = run;
    #pragma unroll
    for (int o = 1; o < 32; o <<= 1) {
        const int t = __shfl_up_sync(FULLM, s, o);
        if (lane >= o) s += t;
    }
    if (lane == 31) wsum[w] = s;
    __syncthreads();
    if (c == 0) {
        int acc = 0;
        #pragma unroll
        for (int k = 0; k < 8; ++k) { wbase[k] = acc; acc += wsum[k]; }
    }
    __syncthreads();
    const int base = wbase[w] + s - run;
    for (int g = 0; g < NBLKA; ++g) g_off[g * NCELL + c] += base;
}

// ---------------- kC: scatter into sorted packed SoA ----------------
__global__ void kC_scatter(const float2* __restrict__ pos,
                           const float2* __restrict__ vel)
{
    const int e    = blockIdx.x * 256 + threadIdx.x;
    const int cell = g_cellid[e];
    const int dst  = g_off[(e >> 8) * NCELL + cell] + g_lrank[e];
    const float2 p = pos[e];
    const float2 v = vel[e];
    float* P = (float*)g_pos4;
    float* V = (float*)g_vel4;
    const int b = (dst >> 1) * 4 + (dst & 1);
    P[b] = p.x;  P[b + 2] = p.y;
    V[b] = v.x;  V[b + 2] = v.y;
    g_orig[dst] = e;
    ((unsigned char*)g_scellv)[dst] = (unsigned char)cell;
}

// ---------------- k1: cull + compact + pair math + ticketed epilogue ----------------
#define PAIR_BODY(PJ, VJ)                                                     \
    {                                                                         \
        const u64 dx2 = f2add((PJ).x, nxi2);                                  \
        const u64 rxp = f2add(f2add(dx2, C2), nC2);                           \
        const u64 dwx = f2fma(rxp, nOne2, dx2);                               \
        const u64 dy2 = f2add((PJ).y, nyi2);                                  \
        const u64 ryp = f2add(f2add(dy2, C2), nC2);                           \
        const u64 dwy = f2fma(ryp, nOne2, dy2);                               \
        const u64 d2  = f2fma(dwy, dwy, f2mul(dwx, dwx));                     \
        const u64 mp  = f2mask(f2fma(d2, nOne2, perc2c), half2);              \
        const u64 ms  = f2mask(f2fma(d2, nOne2, sep2c),  half2);              \
        Px2 = f2fma(dwx, mp, Px2);                                            \
        Py2 = f2fma(dwy, mp, Py2);                                            \
        Vx2 = f2fma((VJ).x, mp, Vx2);                                         \
        Vy2 = f2fma((VJ).y, mp, Vy2);                                         \
        Cn2 = f2add(Cn2, mp);                                                 \
        Sx2 = f2fma(dwx, ms, Sx2);                                            \
        Sy2 = f2fma(dwy, ms, Sy2);                                            \
    }

__global__ __launch_bounds__(TPB1)
void k1_main(const float2* __restrict__ vel,
             const float2* __restrict__ noise,
             const float*  __restrict__ w_sep,
             const float*  __restrict__ w_ali,
             const float*  __restrict__ w_coh,
             const float*  __restrict__ w_ns,
             float2*       __restrict__ out)
{
    __shared__ unsigned s_mask[8];         // 256-bit live-cell mask
    __shared__ int      s_scan[NWARP];
    __shared__ int      s_total;
    __shared__ int      s_last;
    __shared__ u16      s_pairs[NB / 2];
    __shared__ float    red[NWARP][32][8];

    const int tid    = threadIdx.x;
    const int lane   = tid & 31;
    const int w      = tid >> 5;
    const int g      = blockIdx.x >> 1;    // i-tile
    const int parity = blockIdx.x & 1;
    const int i      = g * 32 + lane;      // every warp holds the same 32 i's

    const float* P = (const float*)g_pos4;
    const float pix = getX(P, i);
    const float piy = getY(P, i);

    // --- tile bbox (each warp computes an identical copy via shuffles) ---
    const float x0 = __shfl_sync(FULLM, pix, 0);
    const float y0 = __shfl_sync(FULLM, piy, 0);
    const float rx = wrap1(pix - x0);
    const float ry = wrap1(piy - y0);
    float mnx = rx, mxx = rx, mny = ry, mxy = ry;
    #pragma unroll
    for (int o = 16; o; o >>= 1) {
        mnx = fminf(mnx, __shfl_xor_sync(FULLM, mnx, o));
        mxx = fmaxf(mxx, __shfl_xor_sync(FULLM, mxx, o));
        mny = fminf(mny, __shfl_xor_sync(FULLM, mny, o));
        mxy = fmaxf(mxy, __shfl_xor_sync(FULLM, mxy, o));
    }
    const float bcx = x0 + 0.5f * (mnx + mxx);
    const float bcy = y0 + 0.5f * (mny + mxy);
    const float bhx = 0.5f * (mxx - mnx);
    const float bhy = 0.5f * (mxy - mny);

    // --- cull: threads 0..255 test static rect of cell tid ---
    if (tid < 256) {
        const int cy = tid >> 4;
        const int lx = tid & 15;
        const int cx = (cy & 1) ? (15 - lx) : lx;
        const float ccx = (cx + 0.5f) * (1.0f / 16.0f);
        const float ccy = (cy + 0.5f) * (1.0f / 16.0f);
        const float gx = fmaxf(0.0f, fabsf(wrap1(bcx - ccx)) - bhx - (1.0f / 32.0f) - 1e-5f);
        const float gy = fmaxf(0.0f, fabsf(wrap1(bcy - ccy)) - bhy - (1.0f / 32.0f) - 1e-5f);
        const bool live = (gx * gx + gy * gy) <= PERC2F;
        const unsigned m = __ballot_sync(FULLM, live);
        if (lane == 0) s_mask[w] = m;
    }
    __syncthreads();

    // --- pair-level liveness: thread t owns pairs [8t, 8t+8) = boids [16t, 16t+16) ---
    unsigned pl = 0;
    {
        const uint4 cv = g_scellv[tid];
        const unsigned cw[4] = {cv.x, cv.y, cv.z, cv.w};
        #pragma unroll
        for (int q = 0; q < 4; ++q) {
            const unsigned word = cw[q];
            #pragma unroll
            for (int h = 0; h < 2; ++h) {
                const unsigned ca = (word >> (h * 16)) & 0xffu;
                const unsigned cb = (word >> (h * 16 + 8)) & 0xffu;
                const unsigned lv = ((s_mask[ca >> 5] >> (ca & 31)) |
                                     (s_mask[cb >> 5] >> (cb & 31))) & 1u;
                pl |= lv << (q * 2 + h);
            }
        }
    }
    const int cntp = __popc(pl);
    int s = cntp;
    #pragma unroll
    for (int o = 1; o < 32; o <<= 1) {
        const int t = __shfl_up_sync(FULLM, s, o);
        if (lane >= o) s += t;
    }
    if (lane == 31) s_scan[w] = s;
    __syncthreads();
    if (tid == 0) {
        int acc = 0;
        #pragma unroll
        for (int k = 0; k < NWARP; ++k) { const int v = s_scan[k]; s_scan[k] = acc; acc += v; }
        s_total = acc;
    }
    __syncthreads();
    {
        int ofs = s_scan[w] + s - cntp;
        unsigned m2 = pl;
        while (m2) {
            const int b = __ffs(m2) - 1;
            m2 &= m2 - 1;
            s_pairs[ofs++] = (u16)(tid * 8 + b);
        }
    }
    __syncthreads();
    const int total = s_total;

    // --- pair loop: this block's warps take segments [parity*16 + w] of 32 ---
    const u64 nxi2   = pack2(-pix, -pix);
    const u64 nyi2   = pack2(-piy, -piy);
    const u64 C2     = pack2( MAGIC,  MAGIC);
    const u64 nC2    = pack2(-MAGIC, -MAGIC);
    const u64 nOne2  = pack2(-1.0f, -1.0f);
    const u64 half2  = pack2(0.5f, 0.5f);
    const u64 sep2c  = pack2(SEP2F, SEP2F);
    const u64 perc2c = pack2(PERC2F, PERC2F);

    u64 Sx2 = 0, Sy2 = 0, Px2 = 0, Py2 = 0, Vx2 = 0, Vy2 = 0, Cn2 = 0;

    const ulonglong2* __restrict__ PP = (const ulonglong2*)g_pos4;
    const ulonglong2* __restrict__ VV = (const ulonglong2*)g_vel4;

    const int sw   = parity * NWARP + w;
    int k          = (total * sw) >> 5;        // NSEG = 32
    const int kend = (total * (sw + 1)) >> 5;

    for (; k + 3 < kend; k += 4) {
        const int i0 = s_pairs[k + 0];
        const int i1 = s_pairs[k + 1];
        const int i2 = s_pairs[k + 2];
        const int i3 = s_pairs[k + 3];
        const ulonglong2 pj0 = PP[i0];
        const ulonglong2 pj1 = PP[i1];
        const ulonglong2 pj2 = PP[i2];
        const ulonglong2 pj3 = PP[i3];
        const ulonglong2 vj0 = VV[i0];
        const ulonglong2 vj1 = VV[i1];
        const ulonglong2 vj2 = VV[i2];
        const ulonglong2 vj3 = VV[i3];
        PAIR_BODY(pj0, vj0)
        PAIR_BODY(pj1, vj1)
        PAIR_BODY(pj2, vj2)
        PAIR_BODY(pj3, vj3)
    }
    for (; k < kend; ++k) {
        const int i0 = s_pairs[k];
        const ulonglong2 pj0 = PP[i0];
        const ulonglong2 vj0 = VV[i0];
        PAIR_BODY(pj0, vj0)
    }

    // --- smem reduce (deterministic within block) ---
    float a, b;
    unpack2(Sx2, a, b);  red[w][lane][0] = a + b;
    unpack2(Sy2, a, b);  red[w][lane][1] = a + b;
    unpack2(Px2, a, b);  red[w][lane][2] = a + b;
    unpack2(Py2, a, b);  red[w][lane][3] = a + b;
    unpack2(Vx2, a, b);  red[w][lane][4] = a + b;
    unpack2(Vy2, a, b);  red[w][lane][5] = a + b;
    unpack2(Cn2, a, b);  red[w][lane][6] = a + b;
    __syncthreads();

    float s7[7];
    if (tid < 32) {
        #pragma unroll
        for (int comp = 0; comp < 7; ++comp) {
            float acc = 0.0f;
            #pragma unroll
            for (int sg = 0; sg < NWARP; ++sg) acc += red[sg][tid][comp];
            s7[comp] = acc;
            g_part[parity][comp][g * 32 + tid] = acc;
        }
        __threadfence();
    }
    __syncthreads();
    if (tid == 0) {
        const int old = atomicAdd(&g_ticket[g], 1);
        s_last = (old == 1);
    }
    __syncthreads();

    if (s_last && tid < 32) {
        __threadfence();
        // combine: value is part0 + part1 (fp add commutative -> same either way)
        #pragma unroll
        for (int comp = 0; comp < 7; ++comp)
            s7[comp] += g_part[1 - parity][comp][g * 32 + tid];

        const float Sx = s7[0], Sy = s7[1], Px = s7[2], Py = s7[3];
        const float Vx = s7[4], Vy = s7[5];
        const float C  = s7[6] - 1.0f;       // remove self

        const int orig = g_orig[g * 32 + tid];
        const float2 vi = vel[orig];
        const float2 nz = noise[orig];

        float nrm = sqrtf(Sx * Sx + Sy * Sy);
        float inv = 1.0f / fmaxf(nrm, EPSF);
        const float sepx = -Sx * inv;
        const float sepy = -Sy * inv;

        const float invC = 1.0f / C;

        const float avx = (Vx - vi.x) * invC - vi.x;
        const float avy = (Vy - vi.y) * invC - vi.y;
        nrm = sqrtf(avx * avx + avy * avy);
        inv = 1.0f / fmaxf(nrm, EPSF);
        const float alix = avx * inv;
        const float aliy = avy * inv;

        const float cx2 = Px * invC;
        const float cy2 = Py * invC;
        nrm = sqrtf(cx2 * cx2 + cy2 * cy2);
        inv = 1.0f / fmaxf(nrm, EPSF);
        const float cohx = cx2 * inv;
        const float cohy = cy2 * inv;

        const float ws = *w_sep;
        const float wa = *w_ali;
        const float wc = *w_coh;
        const float wn = *w_ns;

        float ax = ws * sepx + wa * alix + wc * cohx + wn * nz.x;
        float ay = ws * sepy + wa * aliy + wc * cohy + wn * nz.y;

        nrm = sqrtf(ax * ax + ay * ay);
        if (nrm > 1.0f) {
            const float sc = 1.0f / fmaxf(nrm, EPSF);
            ax *= sc;
            ay *= sc;
        }

        out[orig] = make_float2(ax, ay);
    }
}

extern "C" void kernel_launch(void* const* d_in, const int* in_sizes, int n_in,
                              void* d_out, int out_size)
{
    const float2* pos   = (const float2*)d_in[0];
    const float2* vel   = (const float2*)d_in[1];
    const float2* noise = (const float2*)d_in[2];
    const float*  wsep  = (const float*)d_in[3];
    const float*  wali  = (const float*)d_in[4];
    const float*  wcoh  = (const float*)d_in[5];
    const float*  wns   = (const float*)d_in[6];
    float2* out = (float2*)d_out;

    kA_cells  <<<NBLKA, 256>>>(pos);
    kB_prefix <<<1, 256>>>();
    kC_scatter<<<NBLKA, 256>>>(pos, vel);
    k1_main   <<<NTILE * 2, TPB1>>>(vel, noise, wsep, wali, wcoh, wns, out);
}